// round 5
// baseline (speedup 1.0000x reference)
#include <cuda_runtime.h>
#include <cuda_bf16.h>

// GNN_26242250178821: 2-layer GCN forward.
// out[0] = concat(emb_users, emb_items)
// out[l] = GCNConv(relu?(out[l-1]), Wl, bl), symmetric norm + self loops.
//
// CRITICAL RULE (root cause of rounds 1-4): never pass a __device__ symbol
// as a kernel argument from host code — on GB300 (ATS) the host-shadow
// address is silently writable, so stores vanish into host memory. All g_*
// arrays are referenced only inside device code.

#define D 64
#define MAXN 150016
#define MAXELEM (150016 * 64)

__device__ float g_deg[MAXN];
__device__ float g_dinv[MAXN];
__device__ float g_xw[MAXELEM];
__device__ float g_acc[MAXELEM];
__device__ int   g_idx64;   // 1 if edge_index is int64, 0 if int32

// Probe: int64 indices in [0,150000) have zero high 32 bits in every 8-byte
// word; int32 data packs a second (almost surely nonzero) index there.
__global__ void k_detect(const unsigned long long* __restrict__ p, int nwords) {
    __shared__ int any;
    if (threadIdx.x == 0) any = 0;
    __syncthreads();
    for (int i = threadIdx.x; i < nwords; i += blockDim.x)
        if ((p[i] >> 32) != 0ull) any = 1;
    __syncthreads();
    if (threadIdx.x == 0) g_idx64 = any ? 0 : 1;
}

__device__ __forceinline__ int load_idx(const void* ei, long long i) {
    if (g_idx64) return (int)((const long long*)ei)[i];
    return ((const int*)ei)[i];
}

__global__ void k_zero(int n, int nd) {
    int i = blockIdx.x * blockDim.x + threadIdx.x;
    if (i < nd) g_acc[i] = 0.0f;
    if (i < n)  g_deg[i] = 0.0f;
}

__global__ void k_count_deg(const void* __restrict__ ei, int e, int n) {
    int i = blockIdx.x * blockDim.x + threadIdx.x;
    if (i < e) {
        int c = load_idx(ei, (long long)e + i);   // col half
        if ((unsigned)c < (unsigned)n) atomicAdd(&g_deg[c], 1.0f);
    }
}

__global__ void k_dinv(int n) {
    int i = blockIdx.x * blockDim.x + threadIdx.x;
    if (i < n) g_dinv[i] = rsqrtf(g_deg[i] + 1.0f);
}

// layer0 = concat(users, items) as float4
__global__ void k_concat(const float4* __restrict__ u, const float4* __restrict__ it,
                         float4* __restrict__ out0, int nu4, int tot4) {
    int i = blockIdx.x * blockDim.x + threadIdx.x;
    if (i < tot4) out0[i] = (i < nu4) ? u[i] : it[i - nu4];
}

// g_xw[n,64] = (relu? max(x,0) : x)[n,64] @ W[64,64]
// Output array referenced internally (device symbol), never via host arg.
__global__ void k_gemm64(const float* __restrict__ x, const float* __restrict__ W,
                         int n, int relu_in) {
    __shared__ float Ws[64 * 64];
    __shared__ float xs[64 * 64];
    int tid = threadIdx.x;
    int row0 = blockIdx.x * 64;
    int nr = n - row0; if (nr > 64) nr = 64;

    for (int i = tid; i < 64 * 64; i += 256) Ws[i] = W[i];
    for (int i = tid; i < nr * 64; i += 256) {
        float v = x[(size_t)row0 * 64 + i];
        if (relu_in) v = fmaxf(v, 0.0f);
        xs[i] = v;
    }
    __syncthreads();

    int c = tid & 63;
    for (int r = tid >> 6; r < nr; r += 4) {
        float acc = 0.0f;
        #pragma unroll
        for (int k = 0; k < 64; k++) acc += xs[r * 64 + k] * Ws[k * 64 + c];
        g_xw[(size_t)(row0 + r) * 64 + c] = acc;
    }
}

// g_acc[col] += g_xw[row] * dinv[row]*dinv[col]; one warp per edge.
__global__ void k_scatter(const void* __restrict__ ei, int e, int n) {
    int lane = threadIdx.x & 31;
    int w = (blockIdx.x * blockDim.x + threadIdx.x) >> 5;
    if (w >= e) return;
    int r = load_idx(ei, w);
    int c = load_idx(ei, (long long)e + w);
    if ((unsigned)r < (unsigned)n && (unsigned)c < (unsigned)n) {
        float coef = g_dinv[r] * g_dinv[c];
        const float* src = g_xw + (size_t)r * 64;
        float* dst = g_acc + (size_t)c * 64;
        atomicAdd(dst + lane,      src[lane]      * coef);
        atomicAdd(dst + lane + 32, src[lane + 32] * coef);
    }
}

// out = g_acc + g_xw*dinv^2 + b; also reset g_acc for next layer.
__global__ void k_finalize(const float* __restrict__ b, float* __restrict__ out, int nd) {
    int idx = blockIdx.x * blockDim.x + threadIdx.x;
    if (idx < nd) {
        int i = idx >> 6, d = idx & 63;
        float di = g_dinv[i];
        out[idx] = g_acc[idx] + g_xw[idx] * di * di + b[d];
        g_acc[idx] = 0.0f;
    }
}

extern "C" void kernel_launch(void* const* d_in, const int* in_sizes, int n_in,
                              void* d_out, int out_size) {
    const float* emb_users = (const float*)d_in[0];
    const float* emb_items = (const float*)d_in[1];
    const float* W1 = (const float*)d_in[2];
    const float* b1 = (const float*)d_in[3];
    const float* W2 = (const float*)d_in[4];
    const float* b2 = (const float*)d_in[5];
    const void*  ei = d_in[6];

    int NU = in_sizes[0] / D;
    int NI = in_sizes[1] / D;
    int N  = NU + NI;
    int E  = in_sizes[6] / 2;
    int ND = N * D;

    float* out0 = (float*)d_out;
    float* out1 = out0 + (size_t)N * D;
    float* out2 = out1 + (size_t)N * D;

    const int T = 256;
    int gN  = (N + T - 1) / T;
    int gND = (ND + T - 1) / T;
    int gE  = (E + T - 1) / T;
    int gS  = (int)(((long long)E * 32 + T - 1) / T);

    k_detect<<<1, 256>>>((const unsigned long long*)ei, 256);

    k_zero<<<gND, T>>>(N, ND);
    k_count_deg<<<gE, T>>>(ei, E, N);
    k_dinv<<<gN, T>>>(N);

    int nu4 = NU * (D / 4), tot4 = N * (D / 4);
    k_concat<<<(tot4 + T - 1) / T, T>>>((const float4*)emb_users,
                                        (const float4*)emb_items,
                                        (float4*)out0, nu4, tot4);

    // layer 1
    k_gemm64<<<(N + 63) / 64, T>>>(out0, W1, N, 0);
    k_scatter<<<gS, T>>>(ei, E, N);
    k_finalize<<<gND, T>>>(b1, out1, ND);

    // layer 2 (relu applied on read of out1)
    k_gemm64<<<(N + 63) / 64, T>>>(out1, W2, N, 1);
    k_scatter<<<gS, T>>>(ei, E, N);
    k_finalize<<<gND, T>>>(b2, out2, ND);
}

// round 6
// speedup vs baseline: 1.6991x; 1.6991x over previous
#include <cuda_runtime.h>
#include <cuda_bf16.h>

// GNN_26242250178821: 2-layer GCN forward, CSR-gather formulation.
// out[0] = concat(emb_users, emb_items)
// out[l] = GCNConv(relu?(out[l-1]), Wl, bl), symmetric norm + self loops.
//
// Pipeline: deg histogram -> scan -> CSR build (src,coef per edge) ->
// per layer: gemm -> warp-per-node gather aggregation fused with epilogue.
//
// RULE (root cause of earlier rounds): never pass a __device__ symbol as a
// kernel argument from host code — on GB300/ATS the host-shadow address is
// silently writable. All g_* arrays referenced only inside device code.

#define D 64
#define MAXN 150016
#define MAXE  3000064
#define MAXELEM (150016 * 64)

__device__ int   g_deg[MAXN];
__device__ int   g_off[MAXN + 1];
__device__ int   g_pos[MAXN];
__device__ float g_dinv[MAXN];
__device__ int   g_src[MAXE];
__device__ float g_coef[MAXE];
__device__ float g_xw[MAXELEM];
__device__ int   g_idx64;   // 1 if edge_index is int64, 0 if int32

// Probe: int64 indices in [0,150000) have zero high 32 bits in every 8-byte
// word; int32 data packs a second (almost surely nonzero) index there.
__global__ void k_detect(const unsigned long long* __restrict__ p, int nwords) {
    __shared__ int any;
    if (threadIdx.x == 0) any = 0;
    __syncthreads();
    for (int i = threadIdx.x; i < nwords; i += blockDim.x)
        if ((p[i] >> 32) != 0ull) any = 1;
    __syncthreads();
    if (threadIdx.x == 0) g_idx64 = any ? 0 : 1;
}

__device__ __forceinline__ int load_idx(const void* ei, long long i) {
    if (g_idx64) return (int)((const long long*)ei)[i];
    return ((const int*)ei)[i];
}

__global__ void k_zero_deg(int n) {
    int i = blockIdx.x * blockDim.x + threadIdx.x;
    if (i < n) g_deg[i] = 0;
}

__global__ void k_count_deg(const void* __restrict__ ei, int e, int n) {
    int i = blockIdx.x * blockDim.x + threadIdx.x;
    if (i < e) {
        int c = load_idx(ei, (long long)e + i);   // col half
        if ((unsigned)c < (unsigned)n) atomicAdd(&g_deg[c], 1);
    }
}

__global__ void k_dinv(int n) {
    int i = blockIdx.x * blockDim.x + threadIdx.x;
    if (i < n) g_dinv[i] = rsqrtf((float)g_deg[i] + 1.0f);
}

// Single-block (1024 threads) exclusive scan of g_deg into g_off and g_pos.
__global__ void k_scan(int n) {
    __shared__ int warp_sums[32];
    int tid = threadIdx.x;
    int chunk = (n + 1023) / 1024;
    int start = tid * chunk;
    int end = start + chunk; if (end > n) end = n;
    int s = 0;
    for (int i = start; i < end; i++) s += g_deg[i];

    int lane = tid & 31, wid = tid >> 5;
    int v = s;
    #pragma unroll
    for (int o = 1; o < 32; o <<= 1) {
        int t = __shfl_up_sync(~0u, v, o);
        if (lane >= o) v += t;
    }
    if (lane == 31) warp_sums[wid] = v;
    __syncthreads();
    if (wid == 0) {
        int w = warp_sums[lane];
        #pragma unroll
        for (int o = 1; o < 32; o <<= 1) {
            int t = __shfl_up_sync(~0u, w, o);
            if (lane >= o) w += t;
        }
        warp_sums[lane] = w;
    }
    __syncthreads();
    int excl = v - s + (wid > 0 ? warp_sums[wid - 1] : 0);

    int run = excl;
    for (int i = start; i < end; i++) {
        g_off[i] = run;
        g_pos[i] = run;
        run += g_deg[i];
    }
    if (tid == 1023) g_off[n] = run;  // run==total even for an empty chunk
}

// Bucket edges: g_src[p]=row, g_coef[p]=dinv[row]*dinv[col].
__global__ void k_build(const void* __restrict__ ei, int e, int n) {
    int i = blockIdx.x * blockDim.x + threadIdx.x;
    if (i < e) {
        int r = load_idx(ei, i);
        int c = load_idx(ei, (long long)e + i);
        if ((unsigned)r < (unsigned)n && (unsigned)c < (unsigned)n) {
            int p = atomicAdd(&g_pos[c], 1);
            g_src[p] = r;
            g_coef[p] = g_dinv[r] * g_dinv[c];
        }
    }
}

// layer0 = concat(users, items) as float4
__global__ void k_concat(const float4* __restrict__ u, const float4* __restrict__ it,
                         float4* __restrict__ out0, int nu4, int tot4) {
    int i = blockIdx.x * blockDim.x + threadIdx.x;
    if (i < tot4) out0[i] = (i < nu4) ? u[i] : it[i - nu4];
}

// g_xw[n,64] = (relu? max(x,0) : x)[n,64] @ W[64,64]
__global__ void k_gemm64(const float* __restrict__ x, const float* __restrict__ W,
                         int n, int relu_in) {
    __shared__ float Ws[64 * 64];
    __shared__ float xs[64 * 64];
    int tid = threadIdx.x;
    int row0 = blockIdx.x * 64;
    int nr = n - row0; if (nr > 64) nr = 64;

    for (int i = tid; i < 64 * 64; i += 256) Ws[i] = W[i];
    for (int i = tid; i < nr * 64; i += 256) {
        float v = x[(size_t)row0 * 64 + i];
        if (relu_in) v = fmaxf(v, 0.0f);
        xs[i] = v;
    }
    __syncthreads();

    int c = tid & 63;
    for (int r = tid >> 6; r < nr; r += 4) {
        float acc = 0.0f;
        #pragma unroll
        for (int k = 0; k < 64; k++) acc += xs[r * 64 + k] * Ws[k * 64 + c];
        g_xw[(size_t)(row0 + r) * 64 + c] = acc;
    }
}

// Warp per node: out[i] = sum_{edges p->i} xw[src[p]]*coef[p]
//                        + xw[i]*dinv[i]^2 + b
__global__ void k_agg(const float* __restrict__ b, float* __restrict__ out, int n) {
    int i = (blockIdx.x * blockDim.x + threadIdx.x) >> 5;
    int lane = threadIdx.x & 31;
    if (i >= n) return;

    int p = g_off[i];
    int pend = g_off[i + 1];
    float acc0 = 0.0f, acc1 = 0.0f;

    if (p < pend) {
        int r = g_src[p];
        float cf = g_coef[p];
        for (; p + 1 < pend; p++) {
            int rn = g_src[p + 1];          // prefetch next edge metadata
            float cn = g_coef[p + 1];
            const float* src = g_xw + (size_t)r * 64;
            acc0 += src[lane]      * cf;
            acc1 += src[lane + 32] * cf;
            r = rn; cf = cn;
        }
        const float* src = g_xw + (size_t)r * 64;
        acc0 += src[lane]      * cf;
        acc1 += src[lane + 32] * cf;
    }

    float di = g_dinv[i];
    float d2 = di * di;
    size_t base = (size_t)i * 64;
    out[base + lane]      = acc0 + g_xw[base + lane]      * d2 + b[lane];
    out[base + lane + 32] = acc1 + g_xw[base + lane + 32] * d2 + b[lane + 32];
}

extern "C" void kernel_launch(void* const* d_in, const int* in_sizes, int n_in,
                              void* d_out, int out_size) {
    const float* emb_users = (const float*)d_in[0];
    const float* emb_items = (const float*)d_in[1];
    const float* W1 = (const float*)d_in[2];
    const float* b1 = (const float*)d_in[3];
    const float* W2 = (const float*)d_in[4];
    const float* b2 = (const float*)d_in[5];
    const void*  ei = d_in[6];

    int NU = in_sizes[0] / D;
    int NI = in_sizes[1] / D;
    int N  = NU + NI;
    int E  = in_sizes[6] / 2;

    float* out0 = (float*)d_out;
    float* out1 = out0 + (size_t)N * D;
    float* out2 = out1 + (size_t)N * D;

    const int T = 256;
    int gN = (N + T - 1) / T;
    int gE = (E + T - 1) / T;
    int gW = (int)(((long long)N * 32 + T - 1) / T);   // warp per node

    k_detect<<<1, 256>>>((const unsigned long long*)ei, 256);

    k_zero_deg<<<gN, T>>>(N);
    k_count_deg<<<gE, T>>>(ei, E, N);
    k_dinv<<<gN, T>>>(N);
    k_scan<<<1, 1024>>>(N);
    k_build<<<gE, T>>>(ei, E, N);

    int nu4 = NU * (D / 4), tot4 = N * (D / 4);
    k_concat<<<(tot4 + T - 1) / T, T>>>((const float4*)emb_users,
                                        (const float4*)emb_items,
                                        (float4*)out0, nu4, tot4);

    // layer 1
    k_gemm64<<<(N + 63) / 64, T>>>(out0, W1, N, 0);
    k_agg<<<gW, T>>>(b1, out1, N);

    // layer 2 (relu applied on read of out1)
    k_gemm64<<<(N + 63) / 64, T>>>(out1, W2, N, 1);
    k_agg<<<gW, T>>>(b2, out2, N);
}

// round 7
// speedup vs baseline: 1.8092x; 1.0648x over previous
#include <cuda_runtime.h>
#include <cuda_fp16.h>
#include <cuda_bf16.h>

// GNN_26242250178821: 2-layer GCN forward, CSR-gather + fp16 feature rows.
// out[0] = concat(emb_users, emb_items)
// out[l] = GCNConv(relu?(out[l-1]), Wl, bl), symmetric norm + self loops.
//
// RULE (root cause of earlier rounds): never pass a __device__ symbol as a
// kernel argument from host code — on GB300/ATS the host-shadow address is
// silently writable. All g_* arrays referenced only inside device code.

#define D 64
#define MAXN 150016
#define MAXE  3000064
#define MAXELEM (150016 * 64)

__device__ int    g_deg[MAXN];
__device__ int    g_off[MAXN + 1];
__device__ int    g_pos[MAXN];
__device__ float  g_dinv[MAXN];
__device__ unsigned long long g_edge[MAXE];  // (coef bits << 32) | src
__device__ __half g_xwh[MAXELEM];            // xw rows in fp16 (128 B/row)
__device__ int    g_idx64;                   // 1 if edge_index is int64

// Probe: int64 indices in [0,150000) have zero high 32 bits in every 8-byte
// word; int32 data packs a second (almost surely nonzero) index there.
__global__ void k_detect(const unsigned long long* __restrict__ p, int nwords) {
    __shared__ int any;
    if (threadIdx.x == 0) any = 0;
    __syncthreads();
    for (int i = threadIdx.x; i < nwords; i += blockDim.x)
        if ((p[i] >> 32) != 0ull) any = 1;
    __syncthreads();
    if (threadIdx.x == 0) g_idx64 = any ? 0 : 1;
}

__device__ __forceinline__ int load_idx(const void* ei, long long i) {
    if (g_idx64) return (int)((const long long*)ei)[i];
    return ((const int*)ei)[i];
}

__global__ void k_zero_deg(int n) {
    int i = blockIdx.x * blockDim.x + threadIdx.x;
    if (i < n) g_deg[i] = 0;
}

__global__ void k_count_deg(const void* __restrict__ ei, int e, int n) {
    int i = blockIdx.x * blockDim.x + threadIdx.x;
    if (i < e) {
        int c = load_idx(ei, (long long)e + i);   // col half
        if ((unsigned)c < (unsigned)n) atomicAdd(&g_deg[c], 1);
    }
}

__global__ void k_dinv(int n) {
    int i = blockIdx.x * blockDim.x + threadIdx.x;
    if (i < n) g_dinv[i] = rsqrtf((float)g_deg[i] + 1.0f);
}

// Single-block (1024 threads) exclusive scan of g_deg into g_off and g_pos.
__global__ void k_scan(int n) {
    __shared__ int warp_sums[32];
    int tid = threadIdx.x;
    int chunk = (n + 1023) / 1024;
    int start = tid * chunk;
    int end = start + chunk; if (end > n) end = n;
    int s = 0;
    for (int i = start; i < end; i++) s += g_deg[i];

    int lane = tid & 31, wid = tid >> 5;
    int v = s;
    #pragma unroll
    for (int o = 1; o < 32; o <<= 1) {
        int t = __shfl_up_sync(~0u, v, o);
        if (lane >= o) v += t;
    }
    if (lane == 31) warp_sums[wid] = v;
    __syncthreads();
    if (wid == 0) {
        int w = warp_sums[lane];
        #pragma unroll
        for (int o = 1; o < 32; o <<= 1) {
            int t = __shfl_up_sync(~0u, w, o);
            if (lane >= o) w += t;
        }
        warp_sums[lane] = w;
    }
    __syncthreads();
    int excl = v - s + (wid > 0 ? warp_sums[wid - 1] : 0);

    int run = excl;
    for (int i = start; i < end; i++) {
        g_off[i] = run;
        g_pos[i] = run;
        run += g_deg[i];
    }
    if (tid == 1023) g_off[n] = run;  // run==total even for an empty chunk
}

// Bucket edges: one scattered 8-byte store per edge.
__global__ void k_build(const void* __restrict__ ei, int e, int n) {
    int i = blockIdx.x * blockDim.x + threadIdx.x;
    if (i < e) {
        int r = load_idx(ei, i);
        int c = load_idx(ei, (long long)e + i);
        if ((unsigned)r < (unsigned)n && (unsigned)c < (unsigned)n) {
            int p = atomicAdd(&g_pos[c], 1);
            float cf = g_dinv[r] * g_dinv[c];
            g_edge[p] = ((unsigned long long)__float_as_uint(cf) << 32)
                        | (unsigned)r;
        }
    }
}

// layer0 = concat(users, items) as float4
__global__ void k_concat(const float4* __restrict__ u, const float4* __restrict__ it,
                         float4* __restrict__ out0, int nu4, int tot4) {
    int i = blockIdx.x * blockDim.x + threadIdx.x;
    if (i < tot4) out0[i] = (i < nu4) ? u[i] : it[i - nu4];
}

// g_xwh[n,64] = fp16( (relu? max(x,0) : x)[n,64] @ W[64,64] )
__global__ void k_gemm64(const float* __restrict__ x, const float* __restrict__ W,
                         int n, int relu_in) {
    __shared__ float Ws[64 * 64];
    __shared__ float xs[64 * 64];
    int tid = threadIdx.x;
    int row0 = blockIdx.x * 64;
    int nr = n - row0; if (nr > 64) nr = 64;

    for (int i = tid; i < 64 * 64; i += 256) Ws[i] = W[i];
    for (int i = tid; i < nr * 64; i += 256) {
        float v = x[(size_t)row0 * 64 + i];
        if (relu_in) v = fmaxf(v, 0.0f);
        xs[i] = v;
    }
    __syncthreads();

    int c = tid & 63;
    for (int r = tid >> 6; r < nr; r += 4) {
        float acc = 0.0f;
        #pragma unroll
        for (int k = 0; k < 64; k++) acc += xs[r * 64 + k] * Ws[k * 64 + c];
        g_xwh[(size_t)(row0 + r) * 64 + c] = __float2half(acc);
    }
}

// Warp per node. Lane owns dims {2*lane, 2*lane+1} (one half2 = 4B per lane,
// 128B per row -> exactly one coalesced LDG per edge). Edge metadata loaded
// coalesced 32-at-a-time and distributed via 64-bit shuffle.
__global__ void k_agg(const float* __restrict__ b, float* __restrict__ out, int n) {
    int node = (blockIdx.x * blockDim.x + threadIdx.x) >> 5;
    int lane = threadIdx.x & 31;
    if (node >= n) return;

    int p0 = g_off[node];
    int p1 = g_off[node + 1];
    float acc0 = 0.0f, acc1 = 0.0f;

    const __half2* xw2 = (const __half2*)g_xwh;

    for (int base = p0; base < p1; base += 32) {
        int cnt = p1 - base; if (cnt > 32) cnt = 32;
        unsigned long long meta = 0;
        if (base + lane < p1) meta = g_edge[base + lane];
        #pragma unroll 4
        for (int j = 0; j < cnt; j++) {
            unsigned long long m = __shfl_sync(~0u, meta, j);
            int r = (int)(unsigned)m;
            float cf = __uint_as_float((unsigned)(m >> 32));
            float2 f = __half22float2(xw2[(size_t)r * 32 + lane]);
            acc0 += f.x * cf;
            acc1 += f.y * cf;
        }
    }

    float di = g_dinv[node];
    float d2 = di * di;
    float2 fs = __half22float2(xw2[(size_t)node * 32 + lane]);
    float2 bb = ((const float2*)b)[lane];
    float2 o;
    o.x = acc0 + fs.x * d2 + bb.x;
    o.y = acc1 + fs.y * d2 + bb.y;
    ((float2*)out)[(size_t)node * 32 + lane] = o;
}

extern "C" void kernel_launch(void* const* d_in, const int* in_sizes, int n_in,
                              void* d_out, int out_size) {
    const float* emb_users = (const float*)d_in[0];
    const float* emb_items = (const float*)d_in[1];
    const float* W1 = (const float*)d_in[2];
    const float* b1 = (const float*)d_in[3];
    const float* W2 = (const float*)d_in[4];
    const float* b2 = (const float*)d_in[5];
    const void*  ei = d_in[6];

    int NU = in_sizes[0] / D;
    int NI = in_sizes[1] / D;
    int N  = NU + NI;
    int E  = in_sizes[6] / 2;

    float* out0 = (float*)d_out;
    float* out1 = out0 + (size_t)N * D;
    float* out2 = out1 + (size_t)N * D;

    const int T = 256;
    int gN = (N + T - 1) / T;
    int gE = (E + T - 1) / T;
    int gW = (int)(((long long)N * 32 + T - 1) / T);   // warp per node

    k_detect<<<1, 256>>>((const unsigned long long*)ei, 256);

    k_zero_deg<<<gN, T>>>(N);
    k_count_deg<<<gE, T>>>(ei, E, N);
    k_dinv<<<gN, T>>>(N);
    k_scan<<<1, 1024>>>(N);
    k_build<<<gE, T>>>(ei, E, N);

    int nu4 = NU * (D / 4), tot4 = N * (D / 4);
    k_concat<<<(tot4 + T - 1) / T, T>>>((const float4*)emb_users,
                                        (const float4*)emb_items,
                                        (float4*)out0, nu4, tot4);

    // layer 1
    k_gemm64<<<(N + 63) / 64, T>>>(out0, W1, N, 0);
    k_agg<<<gW, T>>>(b1, out1, N);

    // layer 2 (relu applied on read of out1)
    k_gemm64<<<(N + 63) / 64, T>>>(out1, W2, N, 1);
    k_agg<<<gW, T>>>(b2, out2, N);
}

// round 8
// speedup vs baseline: 1.8772x; 1.0376x over previous
#include <cuda_runtime.h>
#include <cuda_fp16.h>
#include <cuda_bf16.h>

// GNN_26242250178821: 2-layer GCN forward, CSR-gather + fp16 feature rows,
// register-tiled broadcast GEMM.
//
// RULE (root cause of earlier rounds): never pass a __device__ symbol as a
// kernel argument from host code — on GB300/ATS the host-shadow address is
// silently writable. All g_* arrays referenced only inside device code.

#define D 64
#define MAXN 150016
#define MAXE  3000064
#define MAXELEM (150016 * 64)

__device__ int    g_deg[MAXN];
__device__ int    g_off[MAXN + 1];
__device__ int    g_pos[MAXN];
__device__ float  g_dinv[MAXN];
__device__ unsigned long long g_edge[MAXE];  // (coef bits << 32) | src
__device__ __half g_xwh[MAXELEM];            // xw rows in fp16 (128 B/row)
__device__ int    g_idx64;                   // 1 if edge_index is int64

__global__ void k_detect(const unsigned long long* __restrict__ p, int nwords) {
    __shared__ int any;
    if (threadIdx.x == 0) any = 0;
    __syncthreads();
    for (int i = threadIdx.x; i < nwords; i += blockDim.x)
        if ((p[i] >> 32) != 0ull) any = 1;
    __syncthreads();
    if (threadIdx.x == 0) g_idx64 = any ? 0 : 1;
}

__device__ __forceinline__ int load_idx(const void* ei, long long i) {
    if (g_idx64) return (int)((const long long*)ei)[i];
    return ((const int*)ei)[i];
}

__global__ void k_zero_deg(int n) {
    int i = blockIdx.x * blockDim.x + threadIdx.x;
    if (i < n) g_deg[i] = 0;
}

__global__ void k_count_deg(const void* __restrict__ ei, int e, int n) {
    int i = blockIdx.x * blockDim.x + threadIdx.x;
    if (i < e) {
        int c = load_idx(ei, (long long)e + i);   // col half
        if ((unsigned)c < (unsigned)n) atomicAdd(&g_deg[c], 1);
    }
}

__global__ void k_dinv(int n) {
    int i = blockIdx.x * blockDim.x + threadIdx.x;
    if (i < n) g_dinv[i] = rsqrtf((float)g_deg[i] + 1.0f);
}

// Single-block (1024 threads) exclusive scan of g_deg into g_off and g_pos.
__global__ void k_scan(int n) {
    __shared__ int warp_sums[32];
    int tid = threadIdx.x;
    int chunk = (n + 1023) / 1024;
    int start = tid * chunk;
    int end = start + chunk; if (end > n) end = n;
    int s = 0;
    for (int i = start; i < end; i++) s += g_deg[i];

    int lane = tid & 31, wid = tid >> 5;
    int v = s;
    #pragma unroll
    for (int o = 1; o < 32; o <<= 1) {
        int t = __shfl_up_sync(~0u, v, o);
        if (lane >= o) v += t;
    }
    if (lane == 31) warp_sums[wid] = v;
    __syncthreads();
    if (wid == 0) {
        int w = warp_sums[lane];
        #pragma unroll
        for (int o = 1; o < 32; o <<= 1) {
            int t = __shfl_up_sync(~0u, w, o);
            if (lane >= o) w += t;
        }
        warp_sums[lane] = w;
    }
    __syncthreads();
    int excl = v - s + (wid > 0 ? warp_sums[wid - 1] : 0);

    int run = excl;
    for (int i = start; i < end; i++) {
        g_off[i] = run;
        g_pos[i] = run;
        run += g_deg[i];
    }
    if (tid == 1023) g_off[n] = run;
}

// Bucket edges: one scattered 8-byte store per edge.
__global__ void k_build(const void* __restrict__ ei, int e, int n) {
    int i = blockIdx.x * blockDim.x + threadIdx.x;
    if (i < e) {
        int r = load_idx(ei, i);
        int c = load_idx(ei, (long long)e + i);
        if ((unsigned)r < (unsigned)n && (unsigned)c < (unsigned)n) {
            int p = atomicAdd(&g_pos[c], 1);
            float cf = g_dinv[r] * g_dinv[c];
            g_edge[p] = ((unsigned long long)__float_as_uint(cf) << 32)
                        | (unsigned)r;
        }
    }
}

// layer0 = concat(users, items) as float4
__global__ void k_concat(const float4* __restrict__ u, const float4* __restrict__ it,
                         float4* __restrict__ out0, int nu4, int tot4) {
    int i = blockIdx.x * blockDim.x + threadIdx.x;
    if (i < tot4) out0[i] = (i < nu4) ? u[i] : it[i - nu4];
}

// Register-tiled GEMM: g_xwh[n,64] = fp16( relu?(x)[n,64] @ W[64,64] ).
// Block: 256 threads, 128 rows. Warp w -> rows [16w,16w+16); lane -> cols
// {lane, lane+32}. Per k: 2 coalesced Ws LDS + 16 broadcast xs LDS, 32 FFMA.
__global__ void __launch_bounds__(256) k_gemm64(
        const float* __restrict__ x, const float* __restrict__ W,
        int n, int relu_in) {
    __shared__ float Ws[64 * 64];
    __shared__ float xs[128 * 64];
    int tid = threadIdx.x;
    int row0 = blockIdx.x * 128;
    int nr = n - row0; if (nr > 128) nr = 128;

    for (int i = tid; i < 4096; i += 256) Ws[i] = W[i];
    {
        const float4* x4 = (const float4*)(x + (size_t)row0 * 64);
        float4* xs4 = (float4*)xs;
        int tot4 = nr * 16;
        for (int i = tid; i < tot4; i += 256) {
            float4 v = x4[i];
            if (relu_in) {
                v.x = fmaxf(v.x, 0.0f); v.y = fmaxf(v.y, 0.0f);
                v.z = fmaxf(v.z, 0.0f); v.w = fmaxf(v.w, 0.0f);
            }
            xs4[i] = v;
        }
        // zero-fill tail rows so unguarded math is benign
        for (int i = nr * 16 + tid; i < 128 * 16; i += 256)
            xs4[i] = make_float4(0.f, 0.f, 0.f, 0.f);
    }
    __syncthreads();

    int warp = tid >> 5, lane = tid & 31;
    int rbase = warp * 16;

    float acc0[16], acc1[16];
    #pragma unroll
    for (int r = 0; r < 16; r++) { acc0[r] = 0.0f; acc1[r] = 0.0f; }

    #pragma unroll 8
    for (int k = 0; k < 64; k++) {
        float w0 = Ws[k * 64 + lane];
        float w1 = Ws[k * 64 + lane + 32];
        #pragma unroll
        for (int r = 0; r < 16; r++) {
            float xv = xs[(rbase + r) * 64 + k];   // warp broadcast
            acc0[r] += xv * w0;
            acc1[r] += xv * w1;
        }
    }

    #pragma unroll
    for (int r = 0; r < 16; r++) {
        int row = rbase + r;
        if (row < nr) {
            size_t base = (size_t)(row0 + row) * 64;
            g_xwh[base + lane]      = __float2half(acc0[r]);
            g_xwh[base + lane + 32] = __float2half(acc1[r]);
        }
    }
}

// Warp per node; lane owns dims {2*lane, 2*lane+1} -> one coalesced 128B
// row load per edge. Edge metadata loaded coalesced, spread via shuffle.
__global__ void k_agg(const float* __restrict__ b, float* __restrict__ out, int n) {
    int node = (blockIdx.x * blockDim.x + threadIdx.x) >> 5;
    int lane = threadIdx.x & 31;
    if (node >= n) return;

    int p0 = g_off[node];
    int p1 = g_off[node + 1];
    float acc0 = 0.0f, acc1 = 0.0f;

    const __half2* xw2 = (const __half2*)g_xwh;

    for (int base = p0; base < p1; base += 32) {
        int cnt = p1 - base; if (cnt > 32) cnt = 32;
        unsigned long long meta = 0;
        if (base + lane < p1) meta = g_edge[base + lane];
        #pragma unroll 4
        for (int j = 0; j < cnt; j++) {
            unsigned long long m = __shfl_sync(~0u, meta, j);
            int r = (int)(unsigned)m;
            float cf = __uint_as_float((unsigned)(m >> 32));
            float2 f = __half22float2(xw2[(size_t)r * 32 + lane]);
            acc0 += f.x * cf;
            acc1 += f.y * cf;
        }
    }

    float di = g_dinv[node];
    float d2 = di * di;
    float2 fs = __half22float2(xw2[(size_t)node * 32 + lane]);
    float2 bb = ((const float2*)b)[lane];
    float2 o;
    o.x = acc0 + fs.x * d2 + bb.x;
    o.y = acc1 + fs.y * d2 + bb.y;
    ((float2*)out)[(size_t)node * 32 + lane] = o;
}

extern "C" void kernel_launch(void* const* d_in, const int* in_sizes, int n_in,
                              void* d_out, int out_size) {
    const float* emb_users = (const float*)d_in[0];
    const float* emb_items = (const float*)d_in[1];
    const float* W1 = (const float*)d_in[2];
    const float* b1 = (const float*)d_in[3];
    const float* W2 = (const float*)d_in[4];
    const float* b2 = (const float*)d_in[5];
    const void*  ei = d_in[6];

    int NU = in_sizes[0] / D;
    int NI = in_sizes[1] / D;
    int N  = NU + NI;
    int E  = in_sizes[6] / 2;

    float* out0 = (float*)d_out;
    float* out1 = out0 + (size_t)N * D;
    float* out2 = out1 + (size_t)N * D;

    const int T = 256;
    int gN = (N + T - 1) / T;
    int gE = (E + T - 1) / T;
    int gW = (int)(((long long)N * 32 + T - 1) / T);   // warp per node

    // Launch order chosen so ncu's fixed capture position lands on k_gemm64.
    // (concat/gemm1 are independent of the edge pipeline.)
    k_detect<<<1, 256>>>((const unsigned long long*)ei, 256);
    k_zero_deg<<<gN, T>>>(N);

    int nu4 = NU * (D / 4), tot4 = N * (D / 4);
    k_concat<<<(tot4 + T - 1) / T, T>>>((const float4*)emb_users,
                                        (const float4*)emb_items,
                                        (float4*)out0, nu4, tot4);

    k_gemm64<<<(N + 127) / 128, T>>>(out0, W1, N, 0);   // capture target

    k_count_deg<<<gE, T>>>(ei, E, N);
    k_dinv<<<gN, T>>>(N);
    k_scan<<<1, 1024>>>(N);
    k_build<<<gE, T>>>(ei, E, N);

    // layer 1 aggregation
    k_agg<<<gW, T>>>(b1, out1, N);

    // layer 2 (relu applied on read of out1)
    k_gemm64<<<(N + 127) / 128, T>>>(out1, W2, N, 1);
    k_agg<<<gW, T>>>(b2, out2, N);
}